// round 9
// baseline (speedup 1.0000x reference)
#include <cuda_runtime.h>

// ---------------------------------------------------------------------------
// 5-layer stacked LSTM, H=51, B=256, T=2048. Output depends only on layer-3 h
// => layers 4,5 dead. 3 roles x 64 batch groups (BT=4) = 192 CTAs, 2 CTAs/SM
// (two INDEPENDENT barrier domains per SM -> latency of one hides under the
// other). Weights in SMEM, conflict-free per-lane reads (lane j reads
// wS[k][j]); h/x via broadcast LDS.128 (dedup). One GEMV row per thread,
// c-state in registers, 2 barriers/step. Role-0 (light) placed on bids
// 148-191 so doubled SMs never get heavy+heavy.
// ---------------------------------------------------------------------------

#define HN 51
#define NJ 204
#define TN 2048
#define NG 64
#define BT 4
#define NSLOT 16
#define XQ 8
#define DPRE 4
#define NTH 256
#define COMM0 224

typedef unsigned long long ull;

__device__ float    g_hbuf[2][NG][NSLOT][HN * BT];
__device__ unsigned g_prod[2][NG];
__device__ unsigned g_cons[2][NG];

__device__ __forceinline__ unsigned ld_acq(const unsigned* p) {
    unsigned v;
    asm volatile("ld.global.acquire.gpu.u32 %0, [%1];" : "=r"(v) : "l"(p));
    return v;
}
__device__ __forceinline__ void st_rel(unsigned* p, unsigned v) {
    asm volatile("st.global.release.gpu.u32 [%0], %1;" :: "l"(p), "r"(v));
}
__device__ __forceinline__ void wait_ge(unsigned* p, unsigned v) {
    if (ld_acq(p) >= v) return;
    while (ld_acq(p) < v) __nanosleep(32);
}
__device__ __forceinline__ float4 ldcg4(const float4* p) {
    float4 v;
    asm volatile("ld.global.cg.v4.f32 {%0,%1,%2,%3}, [%4];"
                 : "=f"(v.x), "=f"(v.y), "=f"(v.z), "=f"(v.w) : "l"(p));
    return v;
}
__device__ __forceinline__ ull ffma2(ull a, ull b, ull c) {
    ull d;
    asm("fma.rn.f32x2 %0, %1, %2, %3;" : "=l"(d) : "l"(a), "l"(b), "l"(c));
    return d;
}
__device__ __forceinline__ ull splat2(float x) {
    ull d; unsigned u = __float_as_uint(x);
    asm("mov.b64 %0, {%1, %2};" : "=l"(d) : "r"(u), "r"(u));
    return d;
}
__device__ __forceinline__ float sigf(float x) {
    return __fdividef(1.f, 1.f + __expf(-x));
}
__device__ __forceinline__ float tanhfast(float x) {
    return 2.f * __fdividef(1.f, 1.f + __expf(-2.f * x)) - 1.f;
}

__global__ void __launch_bounds__(128, 1) reset_kernel() {
    int i = threadIdx.x;
    if (i < NG) {
        g_prod[0][i] = 0; g_prod[1][i] = 0;
        g_cons[0][i] = 0; g_cons[1][i] = 0;
    }
}

__global__ void __launch_bounds__(NTH, 2) lstm_kernel(
    const float* __restrict__ x,    const float* __restrict__ Wih1,
    const float* __restrict__ Whh1, const float* __restrict__ bih1,
    const float* __restrict__ bhh1, const float* __restrict__ Wih,
    const float* __restrict__ Whh,  const float* __restrict__ bih,
    const float* __restrict__ bhh,  const float* __restrict__ Wl,
    const float* __restrict__ bl,   float* __restrict__ out)
{
    extern __shared__ float sm[];
    float* wS     = sm;            // [102][204]  k-major, j fastest (conflict-free)
    float* biasS  = sm + 20808;    // [204]
    float* w1S    = sm + 21012;    // [204]   L1 rank-1 input weights
    float* xq     = sm + 21216;    // [8][51][4]  xin staging ring (1632)
    float* h2     = sm + 22848;    // [2][51][4]  h parity buffers (408)
    float* gates  = sm + 23256;    // [204][4]    (816)
    float* xchunk = sm + 24072;    // [2][32][4]  L1 raw-x windows (256)
    float* wlS    = sm + 24328;    // [51]
    // total 24379 floats = 97516 B

    const int tid = threadIdx.x;
    const int bid = blockIdx.x;
    // role mapping: light role-0 on bids 0-19 and 148-191 (pairs with heavy via
    // classic bid%148 placement); roles 1,2 on bids 20-147.
    int role, g;
    if (bid < 20)       { role = 0; g = bid; }
    else if (bid < 148) { role = 1 + (bid - 20) / 64; g = (bid - 20) % 64; }
    else                { role = 0; g = bid - 148 + 20; }

    // ---------------- one-time loads ----------------
    if (role == 0) {
        for (int i = tid; i < NJ * HN; i += NTH) {
            int j = i / HN, k = i % HN;
            wS[k * NJ + j] = Whh1[i];
        }
        for (int i = tid; i < NJ; i += NTH) {
            biasS[i] = bih1[i] + bhh1[i];
            w1S[i]   = Wih1[i];
        }
        if (tid < 128) {  // first x window
            int q = tid >> 2, b = tid & 3;
            xchunk[q * 4 + b] = x[(size_t)(g * BT + b) * TN + q];
        }
    } else {
        const int l = role - 1;
        for (int i = tid; i < NJ * 2 * HN; i += NTH) {
            int j = i / (2 * HN), k = i % (2 * HN);
            wS[k * NJ + j] = (k < HN) ? Wih[(l * NJ + j) * HN + k]
                                      : Whh[(l * NJ + j) * HN + (k - HN)];
        }
        for (int i = tid; i < NJ; i += NTH)
            biasS[i] = bih[l * NJ + i] + bhh[l * NJ + i];
    }
    if (role == 2 && tid < HN) wlS[tid] = Wl[tid];
    const float blv = (role == 2) ? bl[0] : 0.f;
    for (int i = tid; i < 2 * HN * BT; i += NTH) h2[i] = 0.f;
    __syncthreads();

    const float* ring_in  = (role > 0) ? &g_hbuf[role - 1][g][0][0] : (const float*)0;
    float*       ring_out = (role < 2) ? &g_hbuf[role][g][0][0]     : (float*)0;

    // ---- prologue: comm warp stages xq slots 0..DPRE-1 (persistent skew) ----
    if (role > 0 && tid >= COMM0) {
        for (int d = 0; d < DPRE; d++) {
            if (tid == COMM0) wait_ge(&g_prod[role - 1][g], (unsigned)(d + 1));
            __syncwarp();
            const float4* s4 = (const float4*)(ring_in + d * HN * BT);
            float4* d4 = (float4*)(xq + d * HN * BT);
            for (int i = tid - COMM0; i < HN; i += 32) d4[i] = ldcg4(s4 + i);
            __syncwarp();
            if (tid == COMM0) st_rel(&g_cons[role - 1][g], (unsigned)(d + 1));
        }
    }
    __syncthreads();

    float c_reg = 0.f;

    for (int t = 0; t < TN; t++) {
        const int p  = t & 1;
        const int np = p ^ 1;

        // ================= P0: GEMV (1 row/thread) + comm =================
        if (tid < COMM0) {
            if (tid < NJ) {
                const int j = tid;
                ull acc0 = splat2(biasS[j]);
                ull acc1 = acc0;
                if (role == 0) {
                    const ulonglong2 X =
                        *(const ulonglong2*)&xchunk[(((t >> 5) & 1) * 32 + (t & 31)) * 4];
                    ull w2 = splat2(w1S[j]);
                    acc0 = ffma2(X.x, w2, acc0);
                    acc1 = ffma2(X.y, w2, acc1);
                    const float* hb = h2 + p * HN * BT;
                    #pragma unroll
                    for (int k = 0; k < HN; k++) {
                        ull w = splat2(wS[k * NJ + j]);
                        ulonglong2 H = *(const ulonglong2*)&hb[k * 4];
                        acc0 = ffma2(H.x, w, acc0);
                        acc1 = ffma2(H.y, w, acc1);
                    }
                } else {
                    const float* xb = xq + (t & (XQ - 1)) * HN * BT;
                    #pragma unroll
                    for (int k = 0; k < HN; k++) {
                        ull w = splat2(wS[k * NJ + j]);
                        ulonglong2 X = *(const ulonglong2*)&xb[k * 4];
                        acc0 = ffma2(X.x, w, acc0);
                        acc1 = ffma2(X.y, w, acc1);
                    }
                    const float* hb = h2 + p * HN * BT;
                    #pragma unroll
                    for (int k = 0; k < HN; k++) {
                        ull w = splat2(wS[(HN + k) * NJ + j]);
                        ulonglong2 H = *(const ulonglong2*)&hb[k * 4];
                        acc0 = ffma2(H.x, w, acc0);
                        acc1 = ffma2(H.y, w, acc1);
                    }
                }
                ulonglong2 s; s.x = acc0; s.y = acc1;
                *(ulonglong2*)&gates[j * 4] = s;
            }
        } else {
            const int lane = tid - COMM0;
            if (role > 0 && t + DPRE < TN) {
                if (lane == 0) wait_ge(&g_prod[role - 1][g], (unsigned)(t + DPRE + 1));
                __syncwarp();
                const float4* s4 =
                    (const float4*)(ring_in + ((t + DPRE) & (NSLOT - 1)) * HN * BT);
                float4* d4 = (float4*)(xq + ((t + DPRE) & (XQ - 1)) * HN * BT);
                for (int i = lane; i < HN; i += 32) d4[i] = ldcg4(s4 + i);
                __syncwarp();
                if (lane == 0) st_rel(&g_cons[role - 1][g], (unsigned)(t + DPRE + 1));
            }
            if (role < 2 && t >= NSLOT && lane == 0)
                wait_ge(&g_cons[role][g], (unsigned)(t - (NSLOT - 1)));
            if (role == 0 && (t & 31) == 0 && t + 32 < TN) {
                const int wnext = ((t >> 5) + 1) & 1;
                #pragma unroll
                for (int b = 0; b < BT; b++)
                    xchunk[(wnext * 32 + lane) * 4 + b] =
                        x[(size_t)(g * BT + b) * TN + t + 32 + lane];
            }
            if (role == 2 && t > 0 && lane < BT) {
                const float* hb = h2 + p * HN * BT;   // h3(t-1)
                float a = blv;
                #pragma unroll
                for (int u = 0; u < HN; u++) a += hb[u * 4 + lane] * wlS[u];
                out[(size_t)(g * BT + lane) * TN + (t - 1)] = a;
            }
        }
        __syncthreads();   // gates ready; xq(t+DPRE) landed; backpressure ok

        // ================= P1: cell update (c in registers) =================
        if (tid < NJ) {
            const int u = tid >> 2, b = tid & 3;
            float gi = gates[(         u) * 4 + b];
            float gf = gates[(HN     + u) * 4 + b];
            float gg = gates[(2 * HN + u) * 4 + b];
            float go = gates[(3 * HN + u) * 4 + b];
            c_reg   = sigf(gf) * c_reg + sigf(gi) * tanhfast(gg);
            float h = sigf(go) * tanhfast(c_reg);
            h2[np * HN * BT + tid] = h;
            if (role < 2) ring_out[(t & (NSLOT - 1)) * HN * BT + tid] = h;
        }
        __syncthreads();   // h(t) / ring slot complete
        if (role < 2 && tid == 0) st_rel(&g_prod[role][g], (unsigned)(t + 1));
    }

    // epilogue: out(TN-1) from h3(TN-1), which lives in h2[0] (np of t=2047)
    if (role == 2 && tid >= COMM0 && tid < COMM0 + BT) {
        const int lane = tid - COMM0;
        float a = blv;
        #pragma unroll
        for (int u = 0; u < HN; u++) a += h2[u * 4 + lane] * wlS[u];
        out[(size_t)(g * BT + lane) * TN + (TN - 1)] = a;
    }
}

extern "C" void kernel_launch(void* const* d_in, const int* in_sizes, int n_in,
                              void* d_out, int out_size)
{
    (void)in_sizes; (void)n_in; (void)out_size;
    const float* x    = (const float*)d_in[0];
    const float* Wih1 = (const float*)d_in[1];
    const float* Whh1 = (const float*)d_in[2];
    const float* bih1 = (const float*)d_in[3];
    const float* bhh1 = (const float*)d_in[4];
    const float* Wih  = (const float*)d_in[5];
    const float* Whh  = (const float*)d_in[6];
    const float* bih  = (const float*)d_in[7];
    const float* bhh  = (const float*)d_in[8];
    const float* Wl   = (const float*)d_in[9];
    const float* bl   = (const float*)d_in[10];
    float* out = (float*)d_out;

    const int smem_bytes = 24384 * 4;  // 97536
    cudaFuncSetAttribute(lstm_kernel, cudaFuncAttributeMaxDynamicSharedMemorySize,
                         smem_bytes);

    reset_kernel<<<1, 128>>>();
    lstm_kernel<<<192, NTH, smem_bytes>>>(x, Wih1, Whh1, bih1, bhh1,
                                          Wih, Whh, bih, bhh, Wl, bl, out);
}

// round 10
// speedup vs baseline: 1.3884x; 1.3884x over previous
#include <cuda_runtime.h>

// ---------------------------------------------------------------------------
// 5-layer stacked LSTM, H=51, B=256, T=2048. Output depends only on layer-3 h
// => layers 4,5 dead. 3 roles (L1,L2,L3) x 32 batch groups = 96 CTAs.
// R8 structure (4 gate rows/thread over half-k, 364 LDS/step/SM, reg weights)
// + MUFU-HALVED ACTIVATIONS: all sigmoids/tanhs via one tanh.approx.f32 each;
// the sigmoid's x/2 is pre-folded into i,f,o weights & biases at load time.
// ---------------------------------------------------------------------------

#define HN 51
#define NJ 204
#define TN 2048
#define NG 32
#define BT 8
#define NSLOT 16             // ring slots (power of 2)
#define XBUF 8               // xin SMEM slots (power of 2), > DPRE
#define DPRE 4               // prefetch distance
#define NTH 256
#define COMM0 224            // first tid of comm warp (warp 7)
#define KIT 26               // k iterations per half

typedef unsigned long long ull;

__device__ float    g_hbuf[2][NG][NSLOT][HN * BT];
__device__ unsigned g_prod[2][NG];
__device__ unsigned g_cons[2][NG];

__device__ __forceinline__ unsigned ld_acq(const unsigned* p) {
    unsigned v;
    asm volatile("ld.global.acquire.gpu.u32 %0, [%1];" : "=r"(v) : "l"(p));
    return v;
}
__device__ __forceinline__ void st_rel(unsigned* p, unsigned v) {
    asm volatile("st.global.release.gpu.u32 [%0], %1;" :: "l"(p), "r"(v));
}
__device__ __forceinline__ void wait_ge(unsigned* p, unsigned v) {
    if (ld_acq(p) >= v) return;
    while (ld_acq(p) < v) __nanosleep(32);
}
__device__ __forceinline__ float4 ldcg4(const float4* p) {
    float4 v;
    asm volatile("ld.global.cg.v4.f32 {%0,%1,%2,%3}, [%4];"
                 : "=f"(v.x), "=f"(v.y), "=f"(v.z), "=f"(v.w) : "l"(p));
    return v;
}
__device__ __forceinline__ ull ffma2(ull a, ull b, ull c) {
    ull d;
    asm("fma.rn.f32x2 %0, %1, %2, %3;" : "=l"(d) : "l"(a), "l"(b), "l"(c));
    return d;
}
__device__ __forceinline__ ull splat2(float x) {
    ull d; unsigned u = __float_as_uint(x);
    asm("mov.b64 %0, {%1, %2};" : "=l"(d) : "r"(u), "r"(u));
    return d;
}
__device__ __forceinline__ float tanha(float x) {
    float y;
    asm("tanh.approx.f32 %0, %1;" : "=f"(y) : "f"(x));
    return y;
}
// sigmoid with PRE-HALVED argument: caller provides y = x/2 (folded into W,b)
__device__ __forceinline__ float sig_h(float y) {
    return fmaf(0.5f, tanha(y), 0.5f);
}

__global__ void __launch_bounds__(64, 1) reset_kernel() {
    int i = threadIdx.x;
    if (i < NG) {
        g_prod[0][i] = 0; g_prod[1][i] = 0;
        g_cons[0][i] = 0; g_cons[1][i] = 0;
    }
}

__global__ void __launch_bounds__(NTH, 1) lstm_kernel(
    const float* __restrict__ x,    const float* __restrict__ Wih1,
    const float* __restrict__ Whh1, const float* __restrict__ bih1,
    const float* __restrict__ bhh1, const float* __restrict__ Wih,
    const float* __restrict__ Whh,  const float* __restrict__ bih,
    const float* __restrict__ bhh,  const float* __restrict__ Wl,
    const float* __restrict__ bl,   float* __restrict__ out)
{
    __shared__ __align__(16) float xin[XBUF][HN * BT];  // layer-input slots
    __shared__ __align__(16) float h_t[HN * BT];        // [k][b]
    __shared__ __align__(16) float c_s[HN * BT];
    __shared__ __align__(16) float gbuf[4][NJ * BT];    // partial gates / quadrant
    __shared__ __align__(16) float xchunk[32 * BT];     // [q][b], L1 raw-x prefetch
    __shared__ float wl_s[52];

    const int tid  = threadIdx.x;
    const int role = blockIdx.x / NG;   // 0=L1, 1=L2, 2=L3
    const int g    = blockIdx.x % NG;

    const bool is_comm = (tid >= COMM0);
    const int  cid     = is_comm ? 0 : tid;
    const bool active  = (!is_comm) && (cid < NJ);
    const int  part    = cid / 102;            // 0: input GEMV, 1: recurrent GEMV
    const int  kh      = (cid % 102) / 51;     // k half
    const int  j       = cid % 51;             // hidden unit (gate rows j,51+j,...)
    const int  quad    = part * 2 + kh;
    const int  kbase   = kh * 25;

    // ---------------- per-thread register weights ----------------
    // Gate order: G=0 -> i, G=1 -> f, G=2 -> g, G=3 -> o.
    // i,f,o rows (G != 2) are PRE-SCALED by 0.5 so sigmoid needs only tanh.
    float w_r[4][KIT];
    ull bias2[4], w1_2[4];
    #pragma unroll
    for (int G = 0; G < 4; G++) { bias2[G] = 0; w1_2[G] = 0; }
    #pragma unroll
    for (int G = 0; G < 4; G++)
        #pragma unroll
        for (int k = 0; k < KIT; k++) w_r[G][k] = 0.f;

    if (active) {
        if (part == 1) {
            const float* W = (role == 0) ? Whh1 : (Whh + (role - 1) * NJ * HN);
            #pragma unroll
            for (int G = 0; G < 4; G++) {
                const float sc = (G == 2) ? 1.f : 0.5f;
                #pragma unroll
                for (int k = 0; k < KIT; k++)
                    w_r[G][k] = (k == 0 && kh) ? 0.f
                              : sc * W[(G * 51 + j) * HN + kbase + k];
            }
        } else if (role > 0) {
            const int l = role - 1;
            const float* W = Wih + l * NJ * HN;
            #pragma unroll
            for (int G = 0; G < 4; G++) {
                const float sc = (G == 2) ? 1.f : 0.5f;
                #pragma unroll
                for (int k = 0; k < KIT; k++)
                    w_r[G][k] = (k == 0 && kh) ? 0.f
                              : sc * W[(G * 51 + j) * HN + kbase + k];
            }
            if (kh == 0)
                #pragma unroll
                for (int G = 0; G < 4; G++) {
                    const float sc = (G == 2) ? 1.f : 0.5f;
                    bias2[G] = splat2(sc * (bih[l * NJ + G * 51 + j]
                                          + bhh[l * NJ + G * 51 + j]));
                }
        } else {  // role 0, input part: rank-1 x term (kh==0 lanes only)
            if (kh == 0) {
                #pragma unroll
                for (int G = 0; G < 4; G++) {
                    const float sc = (G == 2) ? 1.f : 0.5f;
                    w1_2[G]  = splat2(sc * Wih1[G * 51 + j]);
                    bias2[G] = splat2(sc * (bih1[G * 51 + j] + bhh1[G * 51 + j]));
                }
            }
        }
    }
    if (role == 2 && tid < HN) wl_s[tid] = Wl[tid];
    const float blv = (role == 2) ? bl[0] : 0.f;
    for (int i = tid; i < HN * BT; i += NTH) { h_t[i] = 0.f; c_s[i] = 0.f; }
    for (int i = tid; i < 4 * NJ * BT; i += NTH) (&gbuf[0][0])[i] = 0.f;
    __syncthreads();

    float*       ring_out = (role < 2) ? &g_hbuf[role][g][0][0]     : (float*)0;
    const float* ring_in  = (role > 0) ? &g_hbuf[role - 1][g][0][0] : (const float*)0;

    // ---- prologue: comm warp prefetches slots 0..DPRE-1 (persistent lead) ----
    if (role > 0 && is_comm) {
        for (int d = 0; d < DPRE; d++) {
            if (tid == COMM0) wait_ge(&g_prod[role - 1][g], (unsigned)(d + 1));
            __syncwarp();
            const float4* src = (const float4*)(ring_in + (d & (NSLOT - 1)) * HN * BT);
            float4* dst = (float4*)xin[d & (XBUF - 1)];
            for (int i = tid - COMM0; i < HN * BT / 4; i += 32) dst[i] = ldcg4(src + i);
            __syncwarp();
            if (tid == COMM0) st_rel(&g_cons[role - 1][g], (unsigned)(d + 1));
        }
    }
    __syncthreads();

    for (int t = 0; t < TN; t++) {
        // ---- L1: refill 32-step x chunk (coalesced), transposed [q][b] ----
        if (role == 0 && (t & 31) == 0) {
            int b = tid >> 5, q = tid & 31;
            xchunk[q * BT + b] = x[(size_t)(g * BT + b) * TN + t + q];
            __syncthreads();
        }

        // ================= P0: 4-row x half-k GEMV tiles + comm =================
        if (!is_comm) {
            if (role == 0 && part == 0) {
                // rank-1 input term, kh==0 lanes only
                if (active && kh == 0) {
                    const ulonglong2* xp = (const ulonglong2*)&xchunk[(t & 31) * BT];
                    ulonglong2 X0 = xp[0], X1 = xp[1];
                    #pragma unroll
                    for (int G = 0; G < 4; G++) {
                        ull a0 = ffma2(X0.x, w1_2[G], bias2[G]);
                        ull a1 = ffma2(X0.y, w1_2[G], bias2[G]);
                        ull a2 = ffma2(X1.x, w1_2[G], bias2[G]);
                        ull a3 = ffma2(X1.y, w1_2[G], bias2[G]);
                        ulonglong2 s0; s0.x = a0; s0.y = a1;
                        ulonglong2 s1; s1.x = a2; s1.y = a3;
                        *(ulonglong2*)&gbuf[0][(G * 51 + j) * BT]     = s0;
                        *(ulonglong2*)&gbuf[0][(G * 51 + j) * BT + 4] = s1;
                    }
                }
            } else {
                const float* base = (part == 0) ? &xin[t & (XBUF - 1)][0] : h_t;
                const ulonglong2* sp = (const ulonglong2*)(base + kbase * BT);
                ull acc[4][4];
                #pragma unroll
                for (int G = 0; G < 4; G++) {
                    acc[G][0] = bias2[G]; acc[G][1] = bias2[G];
                    acc[G][2] = bias2[G]; acc[G][3] = bias2[G];
                }
                #pragma unroll
                for (int k = 0; k < KIT; k++) {
                    ulonglong2 S0 = sp[2 * k], S1 = sp[2 * k + 1];
                    #pragma unroll
                    for (int G = 0; G < 4; G++) {
                        ull w2 = splat2(w_r[G][k]);
                        acc[G][0] = ffma2(S0.x, w2, acc[G][0]);
                        acc[G][1] = ffma2(S0.y, w2, acc[G][1]);
                        acc[G][2] = ffma2(S1.x, w2, acc[G][2]);
                        acc[G][3] = ffma2(S1.y, w2, acc[G][3]);
                    }
                }
                if (active) {
                    #pragma unroll
                    for (int G = 0; G < 4; G++) {
                        ulonglong2 s0; s0.x = acc[G][0]; s0.y = acc[G][1];
                        ulonglong2 s1; s1.x = acc[G][2]; s1.y = acc[G][3];
                        *(ulonglong2*)&gbuf[quad][(G * 51 + j) * BT]     = s0;
                        *(ulonglong2*)&gbuf[quad][(G * 51 + j) * BT + 4] = s1;
                    }
                }
            }
        } else {
            // comm warp: prefetch xin(t+DPRE), backpressure, (L3) output proj
            if (role > 0 && t + DPRE < TN) {
                if (tid == COMM0) wait_ge(&g_prod[role - 1][g], (unsigned)(t + DPRE + 1));
                __syncwarp();
                const float4* src = (const float4*)(ring_in + ((t + DPRE) & (NSLOT - 1)) * HN * BT);
                float4* dst = (float4*)xin[(t + DPRE) & (XBUF - 1)];
                for (int i = tid - COMM0; i < HN * BT / 4; i += 32) dst[i] = ldcg4(src + i);
                __syncwarp();
                if (tid == COMM0) st_rel(&g_cons[role - 1][g], (unsigned)(t + DPRE + 1));
            }
            if (role < 2 && t >= NSLOT && tid == COMM0)
                wait_ge(&g_cons[role][g], (unsigned)(t - (NSLOT - 1)));
            if (role == 2 && t > 0) {
                int b = tid - COMM0;
                if (b < BT) {
                    float a = blv;
                    #pragma unroll
                    for (int u = 0; u < HN; u++) a += h_t[u * BT + b] * wl_s[u];
                    out[(size_t)(g * BT + b) * TN + (t - 1)] = a;
                }
            }
        }
        __syncthreads();   // gates ready; h_t free; xin(t+DPRE) landed

        // ====== P1: cell update (sum quadrants; 1 MUFU.TANH per activation) ====
        for (int i = tid; i < HN * BT; i += NTH) {
            float yi = gbuf[0][i]           + gbuf[1][i]
                     + gbuf[2][i]           + gbuf[3][i];          // = gi/2
            float yf = gbuf[0][HN*BT + i]   + gbuf[1][HN*BT + i]
                     + gbuf[2][HN*BT + i]   + gbuf[3][HN*BT + i];  // = gf/2
            float gg = gbuf[0][2*HN*BT + i] + gbuf[1][2*HN*BT + i]
                     + gbuf[2][2*HN*BT + i] + gbuf[3][2*HN*BT + i];
            float yo = gbuf[0][3*HN*BT + i] + gbuf[1][3*HN*BT + i]
                     + gbuf[2][3*HN*BT + i] + gbuf[3][3*HN*BT + i];  // = go/2
            float c  = sig_h(yf) * c_s[i] + sig_h(yi) * tanha(gg);
            float h  = sig_h(yo) * tanha(c);
            c_s[i] = c;
            h_t[i] = h;
            if (role < 2) ring_out[(t & (NSLOT - 1)) * HN * BT + i] = h;
        }
        __syncthreads();   // h_t / ring slot complete
        if (role < 2 && tid == 0) st_rel(&g_prod[role][g], (unsigned)(t + 1));
    }

    // epilogue: out for t = TN-1 (from final h_t of layer 3)
    if (role == 2 && tid < BT) {
        float a = blv;
        #pragma unroll
        for (int u = 0; u < HN; u++) a += h_t[u * BT + tid] * wl_s[u];
        out[(size_t)(g * BT + tid) * TN + (TN - 1)] = a;
    }
}

extern "C" void kernel_launch(void* const* d_in, const int* in_sizes, int n_in,
                              void* d_out, int out_size)
{
    (void)in_sizes; (void)n_in; (void)out_size;
    const float* x    = (const float*)d_in[0];
    const float* Wih1 = (const float*)d_in[1];
    const float* Whh1 = (const float*)d_in[2];
    const float* bih1 = (const float*)d_in[3];
    const float* bhh1 = (const float*)d_in[4];
    const float* Wih  = (const float*)d_in[5];
    const float* Whh  = (const float*)d_in[6];
    const float* bih  = (const float*)d_in[7];
    const float* bhh  = (const float*)d_in[8];
    const float* Wl   = (const float*)d_in[9];
    const float* bl   = (const float*)d_in[10];
    float* out = (float*)d_out;

    reset_kernel<<<1, 64>>>();
    lstm_kernel<<<3 * NG, NTH>>>(x, Wih1, Whh1, bih1, bhh1,
                                 Wih, Whh, bih, bhh, Wl, bl, out);
}